// round 3
// baseline (speedup 1.0000x reference)
#include <cuda_runtime.h>

// SpatialShift: x (ns=128, m=12, t=784, c=64) fp32.
// ns = b*16 + h*4 + w (H=W=4, shift s=1). Channel d = m*64 + c, fold f=48.
// Pure ns-index permutation => fully coalesced float4 streaming copy.
//
// R3: software pipeline depth 4 (was fully-batched 7) to cut live registers
// to <=32 so __launch_bounds__(256, 8) gives 8 CTAs/SM (100% occ) while
// keeping MLP_eff = 4. Streaming cache hints retained.

// Packed delta tables: 2 bits per group g (0..8), value = delta + 1.
// dh: {+1,-1,0,0,-1,+1,-1,+1, 0}
// dw: { 0, 0,+1,-1,-1,+1,+1,-1, 0}
#define DH_PACK 100434u
#define DW_PACK 75813u

__global__ void __launch_bounds__(256, 8)
spatial_shift_kernel(const float4* __restrict__ x, float4* __restrict__ out) {
    const int c4      = threadIdx.x & 15;   // float4 index within c (0..15)
    const int t_local = threadIdx.x >> 4;   // 0..15

    int blk = blockIdx.x;
    const int tchunk = blk % 7;   blk /= 7;    // 7 * 112 = 784 = t
    const int m      = blk % 12;  blk /= 12;
    const int ns     = blk;                    // 0..127

    const int h = (ns >> 2) & 3;
    const int w = ns & 3;

    const int d = m * 64 + c4 * 4;
    int g = d / 48;
    if (g > 8) g = 8;

    const int dh = (int)((DH_PACK >> (2 * g)) & 3u) - 1;
    const int dw = (int)((DW_PACK >> (2 * g)) & 3u) - 1;

    int hs = h + dh;
    int ws = w + dw;
    bool zero = false;
    if (((unsigned)hs > 3u) || ((unsigned)ws > 3u)) {
        if (g < 4) {
            zero = true;            // axis shifts: out-of-bounds -> 0
        } else {
            hs = h; ws = w;         // diagonal shifts: border -> identity
        }
    }

    const int t0 = tchunk * 112 + t_local;
    // index of float4 for (ns, m, t, c4): ((ns*12 + m)*784 + t)*16 + c4
    float4* o = &out[(((long)(ns * 12 + m)) * 784 + t0) * 16 + c4];

    if (zero) {
        const float4 z = make_float4(0.f, 0.f, 0.f, 0.f);
#pragma unroll
        for (int i = 0; i < 7; i++)
            __stcs(o + i * 256, z);
        return;
    }

    const int ns_src = (ns & ~15) | (hs << 2) | ws;
    const float4* s = &x[(((long)(ns_src * 12 + m)) * 784 + t0) * 16 + c4];

    // Software pipeline, depth 4: 4 loads in flight, store oldest + refill.
    float4 v0 = __ldcs(s + 0 * 256);
    float4 v1 = __ldcs(s + 1 * 256);
    float4 v2 = __ldcs(s + 2 * 256);
    float4 v3 = __ldcs(s + 3 * 256);

    __stcs(o + 0 * 256, v0);  v0 = __ldcs(s + 4 * 256);
    __stcs(o + 1 * 256, v1);  v1 = __ldcs(s + 5 * 256);
    __stcs(o + 2 * 256, v2);  v2 = __ldcs(s + 6 * 256);
    __stcs(o + 3 * 256, v3);
    __stcs(o + 4 * 256, v0);
    __stcs(o + 5 * 256, v1);
    __stcs(o + 6 * 256, v2);
}

extern "C" void kernel_launch(void* const* d_in, const int* in_sizes, int n_in,
                              void* d_out, int out_size) {
    const float4* x = (const float4*)d_in[0];
    float4* out = (float4*)d_out;
    // blocks = 128 * 12 * 7 = 10,752 ; each moves 256 threads * 7 float4
    spatial_shift_kernel<<<10752, 256>>>(x, out);
}

// round 4
// speedup vs baseline: 1.0136x; 1.0136x over previous
#include <cuda_runtime.h>

// SpatialShift: x (ns=128, m=12, t=784, c=64) fp32.
// ns = b*16 + h*4 + w (H=W=4, shift s=1). Channel d = m*64 + c, fold f=48.
// Pure ns-index permutation => fully coalesced float4 streaming copy.
//
// R4: revert to R2's winning shape (7 loads front-batched per thread =
// max bytes-in-flight), but with 32-bit index arithmetic (all offsets
// < 2^31 float4s) to cut register pressure and allow a 7th CTA/SM.

// Packed delta tables: 2 bits per group g (0..8), value = delta + 1.
// dh: {+1,-1,0,0,-1,+1,-1,+1, 0}
// dw: { 0, 0,+1,-1,-1,+1,+1,-1, 0}
#define DH_PACK 100434u
#define DW_PACK 75813u

__global__ void __launch_bounds__(256)
spatial_shift_kernel(const float4* __restrict__ x, float4* __restrict__ out) {
    const int c4      = threadIdx.x & 15;   // float4 index within c (0..15)
    const int t_local = threadIdx.x >> 4;   // 0..15

    int blk = blockIdx.x;
    const int tchunk = blk % 7;   blk /= 7;    // 7 * 112 = 784 = t
    const int m      = blk % 12;  blk /= 12;
    const int ns     = blk;                    // 0..127

    const int h = (ns >> 2) & 3;
    const int w = ns & 3;

    const int d = m * 64 + c4 * 4;
    int g = d / 48;
    if (g > 8) g = 8;

    const int dh = (int)((DH_PACK >> (2 * g)) & 3u) - 1;
    const int dw = (int)((DW_PACK >> (2 * g)) & 3u) - 1;

    int hs = h + dh;
    int ws = w + dw;
    bool zero = false;
    if (((unsigned)hs > 3u) || ((unsigned)ws > 3u)) {
        if (g < 4) {
            zero = true;            // axis shifts: out-of-bounds -> 0
        } else {
            hs = h; ws = w;         // diagonal shifts: border -> identity
        }
    }

    const int t0 = tchunk * 112 + t_local;
    // float4 index of (ns, m, t, c4): ((ns*12 + m)*784 + t)*16 + c4
    // max = 128*12*784*16 = 19,267,584 < 2^31  -> 32-bit offsets are safe.
    const int base_out = ((ns * 12 + m) * 784 + t0) * 16 + c4;

    float4 v[7];
#pragma unroll
    for (int i = 0; i < 7; i++) v[i] = make_float4(0.f, 0.f, 0.f, 0.f);

    if (!zero) {
        const int ns_src   = (ns & ~15) | (hs << 2) | ws;
        const int base_src = ((ns_src * 12 + m) * 784 + t0) * 16 + c4;
#pragma unroll
        for (int i = 0; i < 7; i++)
            v[i] = __ldcs(x + base_src + i * 256);   // +16 t each = 256 float4
    }

#pragma unroll
    for (int i = 0; i < 7; i++)
        __stcs(out + base_out + i * 256, v[i]);
}

extern "C" void kernel_launch(void* const* d_in, const int* in_sizes, int n_in,
                              void* d_out, int out_size) {
    const float4* x = (const float4*)d_in[0];
    float4* out = (float4*)d_out;
    // blocks = 128 * 12 * 7 = 10,752 ; each moves 256 threads * 7 float4
    spatial_shift_kernel<<<10752, 256>>>(x, out);
}